// round 8
// baseline (speedup 1.0000x reference)
#include <cuda_runtime.h>
#include <cuda_bf16.h>
#include <cstdint>

#define Bn    2048
#define CELLn 512
#define Kn    30
#define Ln    1024
#define Vn    80
#define NJ    96
#define KB    8        // K split across blocks in GEMM
#define KCHUNK 64
#define PFR   40       // prefetched onehot rows per k2 block

// partial GEMM sums: g_part[kb][b][j]
__device__ float g_part[KB][Bn][NJ];

__device__ __forceinline__ void cp_async16(unsigned saddr, const void* gptr) {
    asm volatile("cp.async.cg.shared.global [%0], [%1], 16;\n" :: "r"(saddr), "l"(gptr));
}
__device__ __forceinline__ void cp_async_commit() {
    asm volatile("cp.async.commit_group;\n" ::: "memory");
}
__device__ __forceinline__ void cp_async_wait0() {
    asm volatile("cp.async.wait_group 0;\n" ::: "memory");
}

// ---------------------------------------------------------------------------
// k1: partial GEMM  g_part[kb][b][j] = sum_{k in 64-chunk kb} x[b][k] * W[j][k]
//     grid 512 = 64 mb-blocks x 8 kb-splits, 256 threads, single smem stage.
//     Also zero-fills the entire phi output region (overlaps the GEMM latency).
// ---------------------------------------------------------------------------
__global__ __launch_bounds__(256) void k1_gemm(const float* __restrict__ x,
                                               const float* __restrict__ W,
                                               float* __restrict__ out)
{
    __shared__ float4 sW[96 * 17];
    __shared__ float4 sX[32 * 16];

    const int tid  = threadIdx.x;
    const int lane = tid & 31;
    const int w    = tid >> 5;
    const int mb   = blockIdx.x & 63;
    const int kb   = blockIdx.x >> 6;
    const int b0   = mb * 32;
    const int kc4  = (kb * KCHUNK) >> 2;   // float4 offset into K

    // ---- phi zero-fill (independent of GEMM; overlaps load latency) ----
    {
        float4* phi4 = (float4*)(out + (size_t)Bn * Vn + (size_t)Bn * Kn);
        const int total4 = Bn * (Ln + 1) / 4;              // 524800
        const float4 z4 = make_float4(0.f, 0.f, 0.f, 0.f);
        for (int i = blockIdx.x * 256 + tid; i < total4; i += 512 * 256)
            phi4[i] = z4;
    }

    const float4* Wg = (const float4*)W;
    const float4* Xg = (const float4*)x;

    #pragma unroll
    for (int t = 0; t < 6; t++) {
        int i = tid + t * 256;
        int j = i >> 4, c = i & 15;
        if (j < 90) sW[j * 17 + c] = Wg[(size_t)j * (CELLn / 4) + kc4 + c];
    }
    #pragma unroll
    for (int t = 0; t < 2; t++) {
        int i = tid + t * 256;
        int bl = i >> 4, c = i & 15;
        sX[bl * 16 + c] = Xg[(size_t)(b0 + bl) * (CELLn / 4) + kc4 + c];
    }
    __syncthreads();

    float acc[4][3] = {};
    #pragma unroll
    for (int kc = 0; kc < 16; kc++) {
        float4 w0 = sW[(3 * lane + 0) * 17 + kc];
        float4 w1 = sW[(3 * lane + 1) * 17 + kc];
        float4 w2 = sW[(3 * lane + 2) * 17 + kc];
        #pragma unroll
        for (int u = 0; u < 4; u++) {
            float4 xv = sX[(w * 4 + u) * 16 + kc];
            acc[u][0] += xv.x * w0.x + xv.y * w0.y + xv.z * w0.z + xv.w * w0.w;
            acc[u][1] += xv.x * w1.x + xv.y * w1.y + xv.z * w1.z + xv.w * w1.w;
            acc[u][2] += xv.x * w2.x + xv.y * w2.y + xv.z * w2.z + xv.w * w2.w;
        }
    }

    #pragma unroll
    for (int u = 0; u < 4; u++) {
        const int b = b0 + w * 4 + u;
        #pragma unroll
        for (int c = 0; c < 3; c++)
            g_part[kb][b][3 * lane + c] = acc[u][c];
    }
}

// ---------------------------------------------------------------------------
// k2: one block (128 thr) per b.
//  entry : cp.async prefetch of onehots rows [0,40) into smem (12.5 KB)
//  A     : warp0 params finish + window (phi zeros already written by k1)
//  B     : windowed phi (l <= lend only)
//  C     : contraction; rows <40 from smem, tail from gmem at MLP=4
// ---------------------------------------------------------------------------
__global__ __launch_bounds__(128, 12) void k2_fused(
    const float* __restrict__ onehots, const float* __restrict__ kappa_old,
    const float* __restrict__ text_lens, const float* __restrict__ bias,
    float* __restrict__ out)
{
    __shared__ float  s_phi[Ln];          // 4 KB
    __shared__ float4 s_oh[PFR * 20];     // 12.5 KB prefetched onehot rows
    __shared__ float4 s_abk[30];
    __shared__ float4 s_red[4][20];
    __shared__ int    s_lend;

    const int tid  = threadIdx.x;
    const int lane = tid & 31;
    const int wg   = tid >> 5;
    const int b    = blockIdx.x;

    const float4* M4 = (const float4*)onehots + (size_t)b * (Ln * Vn / 4);
    float* phi_out = out + (size_t)Bn * Vn + (size_t)Bn * Kn + (size_t)b * (Ln + 1);

    // ---- prefetch first 40 rows of onehots (contiguous 800 float4) ----
    {
        unsigned sbase = (unsigned)__cvta_generic_to_shared(s_oh);
        #pragma unroll
        for (int t = 0; t < 7; t++) {
            int i = tid + t * 128;
            if (i < PFR * 20) cp_async16(sbase + i * 16, (const void*)(M4 + i));
        }
        cp_async_commit();
    }

    // ---- Phase A: warp0 finishes params + window ----
    if (wg == 0) {
        float wend = 0.0f;
        if (lane < 30) {
            float sa = 0.f, sb = 0.f, sk = 0.f;
            #pragma unroll
            for (int kb = 0; kb < KB; kb++) {
                sa += g_part[kb][b][lane];
                sb += g_part[kb][b][30 + lane];
                sk += g_part[kb][b][60 + lane];
            }
            const float alpha = __expf(sa + bias[lane]);
            const float beta  = __expf(sb + bias[30 + lane]);
            const float kap   = kappa_old[b * Kn + lane] + __expf(sk + bias[60 + lane]);
            out[(size_t)Bn * Vn + (size_t)b * Kn + lane] = kap;
            s_abk[lane] = make_float4(alpha, beta, kap, 0.f);
            wend = kap + sqrtf(110.0f / beta);
        }
        #pragma unroll
        for (int o = 16; o; o >>= 1)
            wend = fmaxf(wend, __shfl_xor_sync(0xffffffffu, wend, o));
        if (lane == 0) s_lend = min((int)ceilf(wend), Ln);
    }
    __syncthreads();

    const int lend = s_lend;
    const float scale = (float)Ln / text_lens[b];

    // ---- Phase B: windowed phi (zeros beyond lend were written by k1) ----
    for (int l = tid; l <= lend; l += 128) {
        const float lf = (float)l;
        float s = 0.0f;
        #pragma unroll 6
        for (int k = 0; k < Kn; k++) {
            float4 p = s_abk[k];
            float d = p.z - lf;
            float gv = -p.y * d * d;
            if (gv > -110.0f) s += p.x * __expf(gv);
        }
        const float v = s * scale;
        phi_out[l] = v;
        if (l < Ln) s_phi[l] = v;
    }
    cp_async_wait0();
    __syncthreads();

    // ---- Phase C: contraction (rows r ≡ wg mod 4, ascending; lanes 0..19 own v) ----
    const int rows = min(lend + 1, Ln);
    if (lane < 20) {
        float4 acc = make_float4(0.f, 0.f, 0.f, 0.f);
        int r = wg;
        const int smax = rows < PFR ? rows : PFR;
        for (; r < smax; r += 4) {
            float4 m = s_oh[r * 20 + lane];
            float p = s_phi[r];
            acc.x += p * m.x; acc.y += p * m.y; acc.z += p * m.z; acc.w += p * m.w;
        }
        const float4* Mp = M4 + (size_t)r * 20 + lane;
        for (; r + 12 < rows; r += 16, Mp += 320) {
            float4 m0 = __ldcs(Mp);
            float4 m1 = __ldcs(Mp + 80);
            float4 m2 = __ldcs(Mp + 160);
            float4 m3 = __ldcs(Mp + 240);
            float p0 = s_phi[r];
            float p1 = s_phi[r + 4];
            float p2 = s_phi[r + 8];
            float p3 = s_phi[r + 12];
            acc.x += p0 * m0.x; acc.y += p0 * m0.y; acc.z += p0 * m0.z; acc.w += p0 * m0.w;
            acc.x += p1 * m1.x; acc.y += p1 * m1.y; acc.z += p1 * m1.z; acc.w += p1 * m1.w;
            acc.x += p2 * m2.x; acc.y += p2 * m2.y; acc.z += p2 * m2.z; acc.w += p2 * m2.w;
            acc.x += p3 * m3.x; acc.y += p3 * m3.y; acc.z += p3 * m3.z; acc.w += p3 * m3.w;
        }
        for (; r < rows; r += 4, Mp += 80) {
            float4 m = __ldcs(Mp);
            float p = s_phi[r];
            acc.x += p * m.x; acc.y += p * m.y; acc.z += p * m.z; acc.w += p * m.w;
        }
        s_red[wg][lane] = acc;
    }
    __syncthreads();

    if (wg == 0 && lane < 20) {
        float4 a0 = s_red[0][lane];
        float4 a1 = s_red[1][lane];
        float4 a2 = s_red[2][lane];
        float4 a3 = s_red[3][lane];
        float4 s;
        s.x = (a0.x + a1.x) + (a2.x + a3.x);
        s.y = (a0.y + a1.y) + (a2.y + a3.y);
        s.z = (a0.z + a1.z) + (a2.z + a3.z);
        s.w = (a0.w + a1.w) + (a2.w + a3.w);
        ((float4*)(out + (size_t)b * Vn))[lane] = s;
    }
}

// ---------------------------------------------------------------------------
extern "C" void kernel_launch(void* const* d_in, const int* in_sizes, int n_in,
                              void* d_out, int out_size)
{
    const float* x         = (const float*)d_in[0];
    const float* kappa_old = (const float*)d_in[1];
    const float* onehots   = (const float*)d_in[2];
    const float* text_lens = (const float*)d_in[3];
    const float* W         = (const float*)d_in[4];
    const float* bias      = (const float*)d_in[5];
    float* out = (float*)d_out;

    k1_gemm<<<512, 256>>>(x, W, out);
    k2_fused<<<Bn, 128>>>(onehots, kappa_old, text_lens, bias, out);
}

// round 10
// speedup vs baseline: 1.0729x; 1.0729x over previous
#include <cuda_runtime.h>
#include <cuda_bf16.h>
#include <cstdint>

#define Bn    2048
#define CELLn 512
#define Kn    30
#define Ln    1024
#define Vn    80
#define NJ    96
#define KB    8        // K split across blocks in GEMM
#define KCHUNK 64
#define PFR   32       // prefetched onehot rows per k2 block

// partial GEMM sums: g_part[kb][b][j]
__device__ float g_part[KB][Bn][NJ];

__device__ __forceinline__ void cp_async16(unsigned saddr, const void* gptr) {
    asm volatile("cp.async.cg.shared.global [%0], [%1], 16;\n" :: "r"(saddr), "l"(gptr));
}
__device__ __forceinline__ void cp_async_commit() {
    asm volatile("cp.async.commit_group;\n" ::: "memory");
}
__device__ __forceinline__ void cp_async_wait0() {
    asm volatile("cp.async.wait_group 0;\n" ::: "memory");
}

// ---------------------------------------------------------------------------
// k1: partial GEMM  g_part[kb][b][j] = sum_{k in 64-chunk kb} x[b][k] * W[j][k]
//     grid 512 = 64 mb-blocks x 8 kb-splits, 256 threads, single smem stage.
// ---------------------------------------------------------------------------
__global__ __launch_bounds__(256) void k1_gemm(const float* __restrict__ x,
                                               const float* __restrict__ W)
{
    __shared__ float4 sW[96 * 17];
    __shared__ float4 sX[32 * 16];

    const int tid  = threadIdx.x;
    const int lane = tid & 31;
    const int w    = tid >> 5;
    const int mb   = blockIdx.x & 63;
    const int kb   = blockIdx.x >> 6;
    const int b0   = mb * 32;
    const int kc4  = (kb * KCHUNK) >> 2;

    const float4* Wg = (const float4*)W;
    const float4* Xg = (const float4*)x;

    #pragma unroll
    for (int t = 0; t < 6; t++) {
        int i = tid + t * 256;
        int j = i >> 4, c = i & 15;
        if (j < 90) sW[j * 17 + c] = Wg[(size_t)j * (CELLn / 4) + kc4 + c];
    }
    #pragma unroll
    for (int t = 0; t < 2; t++) {
        int i = tid + t * 256;
        int bl = i >> 4, c = i & 15;
        sX[bl * 16 + c] = Xg[(size_t)(b0 + bl) * (CELLn / 4) + kc4 + c];
    }
    __syncthreads();

    float acc[4][3] = {};
    #pragma unroll
    for (int kc = 0; kc < 16; kc++) {
        float4 w0 = sW[(3 * lane + 0) * 17 + kc];
        float4 w1 = sW[(3 * lane + 1) * 17 + kc];
        float4 w2 = sW[(3 * lane + 2) * 17 + kc];
        #pragma unroll
        for (int u = 0; u < 4; u++) {
            float4 xv = sX[(w * 4 + u) * 16 + kc];
            acc[u][0] += xv.x * w0.x + xv.y * w0.y + xv.z * w0.z + xv.w * w0.w;
            acc[u][1] += xv.x * w1.x + xv.y * w1.y + xv.z * w1.z + xv.w * w1.w;
            acc[u][2] += xv.x * w2.x + xv.y * w2.y + xv.z * w2.z + xv.w * w2.w;
        }
    }

    #pragma unroll
    for (int u = 0; u < 4; u++) {
        const int b = b0 + w * 4 + u;
        #pragma unroll
        for (int c = 0; c < 3; c++)
            g_part[kb][b][3 * lane + c] = acc[u][c];
    }
}

// ---------------------------------------------------------------------------
// k2: one block (128 thr) per b.
//  entry : cp.async prefetch of onehots rows [0,32) into smem (10 KB)
//  A     : warp0 = params finish + window; warps1-3 = phi row zero-fill
//  B     : windowed phi (l <= lend only)
//  C     : contraction; rows <32 from smem, tail from gmem at MLP=8
// ---------------------------------------------------------------------------
__global__ __launch_bounds__(128, 10) void k2_fused(
    const float* __restrict__ onehots, const float* __restrict__ kappa_old,
    const float* __restrict__ text_lens, const float* __restrict__ bias,
    float* __restrict__ out)
{
    __shared__ float  s_phi[Ln];          // 4 KB
    __shared__ float4 s_oh[PFR * 20];     // 10 KB prefetched onehot rows
    __shared__ float4 s_abk[30];
    __shared__ float4 s_red[4][20];
    __shared__ int    s_lend;

    const int tid  = threadIdx.x;
    const int lane = tid & 31;
    const int wg   = tid >> 5;
    const int b    = blockIdx.x;

    const float4* M4 = (const float4*)onehots + (size_t)b * (Ln * Vn / 4);
    float* phi_out = out + (size_t)Bn * Vn + (size_t)Bn * Kn + (size_t)b * (Ln + 1);

    // ---- prefetch first 32 rows of onehots (contiguous 640 float4) ----
    {
        unsigned sbase = (unsigned)__cvta_generic_to_shared(s_oh);
        #pragma unroll
        for (int t = 0; t < 5; t++) {
            int i = tid + t * 128;
            cp_async16(sbase + i * 16, (const void*)(M4 + i));
        }
        cp_async_commit();
    }

    // ---- Phase A: warp0 params + window; warps1-3 zero-fill phi ----
    if (wg == 0) {
        float wend = 0.0f;
        if (lane < 30) {
            float sa = 0.f, sb = 0.f, sk = 0.f;
            #pragma unroll
            for (int kb = 0; kb < KB; kb++) {
                sa += g_part[kb][b][lane];
                sb += g_part[kb][b][30 + lane];
                sk += g_part[kb][b][60 + lane];
            }
            const float alpha = __expf(sa + bias[lane]);
            const float beta  = __expf(sb + bias[30 + lane]);
            const float kap   = kappa_old[b * Kn + lane] + __expf(sk + bias[60 + lane]);
            out[(size_t)Bn * Vn + (size_t)b * Kn + lane] = kap;
            s_abk[lane] = make_float4(alpha, beta, kap, 0.f);
            wend = kap + sqrtf(110.0f / beta);
        }
        #pragma unroll
        for (int o = 16; o; o >>= 1)
            wend = fmaxf(wend, __shfl_xor_sync(0xffffffffu, wend, o));
        if (lane == 0) s_lend = min((int)ceilf(wend), Ln);
    } else {
        const int zt = tid - 32;               // 0..95
        const int mis = b & 3;
        const int l0  = (4 - mis) & 3;
        const int n4  = (Ln + 1 - l0) >> 2;
        const int tail = Ln + 1 - l0 - (n4 << 2);
        if (zt < l0) phi_out[zt] = 0.0f;
        float4* p4 = (float4*)(phi_out + l0);
        const float4 z4 = make_float4(0.f, 0.f, 0.f, 0.f);
        for (int i = zt; i < n4; i += 96) p4[i] = z4;
        if (zt < tail) phi_out[l0 + (n4 << 2) + zt] = 0.0f;
    }
    __syncthreads();

    const int lend = s_lend;
    const float scale = (float)Ln / text_lens[b];

    // ---- Phase B: windowed phi (overwrites the zeros inside the window) ----
    for (int l = tid; l <= lend; l += 128) {
        const float lf = (float)l;
        float s = 0.0f;
        #pragma unroll 6
        for (int k = 0; k < Kn; k++) {
            float4 p = s_abk[k];
            float d = p.z - lf;
            float gv = -p.y * d * d;
            if (gv > -110.0f) s += p.x * __expf(gv);
        }
        const float v = s * scale;
        phi_out[l] = v;
        if (l < Ln) s_phi[l] = v;
    }
    cp_async_wait0();
    __syncthreads();

    // ---- Phase C: contraction (rows r ≡ wg mod 4, ascending; lanes 0..19 own v) ----
    const int rows = min(lend + 1, Ln);
    if (lane < 20) {
        float4 acc = make_float4(0.f, 0.f, 0.f, 0.f);
        int r = wg;
        const int smax = rows < PFR ? rows : PFR;
        for (; r < smax; r += 4) {
            float4 m = s_oh[r * 20 + lane];
            float p = s_phi[r];
            acc.x += p * m.x; acc.y += p * m.y; acc.z += p * m.z; acc.w += p * m.w;
        }
        const float4* Mp = M4 + (size_t)r * 20 + lane;
        // MLP=8 batches (straggler killer)
        for (; r + 28 < rows; r += 32, Mp += 640) {
            float4 m0 = __ldcs(Mp);
            float4 m1 = __ldcs(Mp + 80);
            float4 m2 = __ldcs(Mp + 160);
            float4 m3 = __ldcs(Mp + 240);
            float4 m4 = __ldcs(Mp + 320);
            float4 m5 = __ldcs(Mp + 400);
            float4 m6 = __ldcs(Mp + 480);
            float4 m7 = __ldcs(Mp + 560);
            float p0 = s_phi[r];
            float p1 = s_phi[r + 4];
            float p2 = s_phi[r + 8];
            float p3 = s_phi[r + 12];
            float p4 = s_phi[r + 16];
            float p5 = s_phi[r + 20];
            float p6 = s_phi[r + 24];
            float p7 = s_phi[r + 28];
            acc.x += p0 * m0.x; acc.y += p0 * m0.y; acc.z += p0 * m0.z; acc.w += p0 * m0.w;
            acc.x += p1 * m1.x; acc.y += p1 * m1.y; acc.z += p1 * m1.z; acc.w += p1 * m1.w;
            acc.x += p2 * m2.x; acc.y += p2 * m2.y; acc.z += p2 * m2.z; acc.w += p2 * m2.w;
            acc.x += p3 * m3.x; acc.y += p3 * m3.y; acc.z += p3 * m3.z; acc.w += p3 * m3.w;
            acc.x += p4 * m4.x; acc.y += p4 * m4.y; acc.z += p4 * m4.z; acc.w += p4 * m4.w;
            acc.x += p5 * m5.x; acc.y += p5 * m5.y; acc.z += p5 * m5.z; acc.w += p5 * m5.w;
            acc.x += p6 * m6.x; acc.y += p6 * m6.y; acc.z += p6 * m6.z; acc.w += p6 * m6.w;
            acc.x += p7 * m7.x; acc.y += p7 * m7.y; acc.z += p7 * m7.z; acc.w += p7 * m7.w;
        }
        // MLP=4 batches
        for (; r + 12 < rows; r += 16, Mp += 320) {
            float4 m0 = __ldcs(Mp);
            float4 m1 = __ldcs(Mp + 80);
            float4 m2 = __ldcs(Mp + 160);
            float4 m3 = __ldcs(Mp + 240);
            float p0 = s_phi[r];
            float p1 = s_phi[r + 4];
            float p2 = s_phi[r + 8];
            float p3 = s_phi[r + 12];
            acc.x += p0 * m0.x; acc.y += p0 * m0.y; acc.z += p0 * m0.z; acc.w += p0 * m0.w;
            acc.x += p1 * m1.x; acc.y += p1 * m1.y; acc.z += p1 * m1.z; acc.w += p1 * m1.w;
            acc.x += p2 * m2.x; acc.y += p2 * m2.y; acc.z += p2 * m2.z; acc.w += p2 * m2.w;
            acc.x += p3 * m3.x; acc.y += p3 * m3.y; acc.z += p3 * m3.z; acc.w += p3 * m3.w;
        }
        for (; r < rows; r += 4, Mp += 80) {
            float4 m = __ldcs(Mp);
            float p = s_phi[r];
            acc.x += p * m.x; acc.y += p * m.y; acc.z += p * m.z; acc.w += p * m.w;
        }
        s_red[wg][lane] = acc;
    }
    __syncthreads();

    if (wg == 0 && lane < 20) {
        float4 a0 = s_red[0][lane];
        float4 a1 = s_red[1][lane];
        float4 a2 = s_red[2][lane];
        float4 a3 = s_red[3][lane];
        float4 s;
        s.x = (a0.x + a1.x) + (a2.x + a3.x);
        s.y = (a0.y + a1.y) + (a2.y + a3.y);
        s.z = (a0.z + a1.z) + (a2.z + a3.z);
        s.w = (a0.w + a1.w) + (a2.w + a3.w);
        ((float4*)(out + (size_t)b * Vn))[lane] = s;
    }
}

// ---------------------------------------------------------------------------
extern "C" void kernel_launch(void* const* d_in, const int* in_sizes, int n_in,
                              void* d_out, int out_size)
{
    const float* x         = (const float*)d_in[0];
    const float* kappa_old = (const float*)d_in[1];
    const float* onehots   = (const float*)d_in[2];
    const float* text_lens = (const float*)d_in[3];
    const float* W         = (const float*)d_in[4];
    const float* bias      = (const float*)d_in[5];
    float* out = (float*)d_out;

    k1_gemm<<<512, 256>>>(x, W);
    k2_fused<<<Bn, 128>>>(onehots, kappa_old, text_lens, bias, out);
}